// round 1
// baseline (speedup 1.0000x reference)
#include <cuda_runtime.h>
#include <math.h>

// ---------------- problem constants ----------------
#define Bb 64
#define Nn 300
#define Cc 256
#define Hh 8
#define HD 32
#define BH (Bb*Hh)          // 512
#define ROWS (Bb*Nn)        // 19200

// ---------------- scratch (device globals; no runtime alloc) ----------------
__device__ float g_q[BH * Nn * HD];     // [b,h,n,d]
__device__ float g_k[BH * Nn * HD];
__device__ float g_v[BH * Nn * HD];
__device__ float g_pos[Hh * Nn * Nn];   // softmaxed positional scores
__device__ float g_oh[ROWS * Cc];       // attention output, [b,n,h*32+d]

// =====================================================================
// Kernel: positional score softmax.  logit[h][n][m] = w0*d + w2*d^2 + b,
// d = m-n (indy term is 0 for a 1x300 patch grid).  One warp per row.
// =====================================================================
__global__ void pos_kernel(const float* __restrict__ Wpos,
                           const float* __restrict__ bpos)
{
    int row  = blockIdx.x * 4 + (threadIdx.x >> 5);   // h*300 + n
    int lane = threadIdx.x & 31;
    if (row >= Hh * Nn) return;
    int h = row / Nn, n = row % Nn;
    float w0 = Wpos[h*3+0], w2 = Wpos[h*3+2], b = bpos[h];

    float s[10], mx = -1e30f;
    #pragma unroll
    for (int t = 0; t < 10; t++) {
        int m = t*32 + lane;
        float v = -1e30f;
        if (m < Nn) { float d = (float)(m - n); v = fmaf(w2*d, d, fmaf(w0, d, b)); }
        s[t] = v; mx = fmaxf(mx, v);
    }
    #pragma unroll
    for (int o = 16; o; o >>= 1) mx = fmaxf(mx, __shfl_xor_sync(0xffffffffu, mx, o));
    float e[10], esum = 0.f;
    #pragma unroll
    for (int t = 0; t < 10; t++) { e[t] = __expf(s[t] - mx); esum += e[t]; }
    #pragma unroll
    for (int o = 16; o; o >>= 1) esum += __shfl_xor_sync(0xffffffffu, esum, o);
    float inv = 1.0f / esum;
    float* dst = g_pos + row * Nn;
    #pragma unroll
    for (int t = 0; t < 10; t++) {
        int m = t*32 + lane;
        if (m < Nn) dst[m] = e[t] * inv;
    }
}

// =====================================================================
// GEMM: out[M,Ncols] = A[M,256] @ W[Ncols,256]^T   (128x128x8 tiles, 8x8/thr)
// mode 0: A=x, W = [Wqk(512 rows); Wv(256 rows)], scatter into g_q/g_k/g_v
// mode 1: A=g_oh, W=Wproj, out = val + bias
// =====================================================================
__global__ __launch_bounds__(256, 2)
void gemm_kernel(const float* __restrict__ A,
                 const float* __restrict__ W0,
                 const float* __restrict__ W1,
                 const float* __restrict__ bias,
                 float* __restrict__ out,
                 int mode)
{
    __shared__ float As[8][132];
    __shared__ float Bs[8][132];

    int tid  = threadIdx.x;
    int row0 = blockIdx.y * 128;
    int col0 = blockIdx.x * 128;
    int tx = tid & 15, ty = tid >> 4;

    const float* Ap = (mode == 0) ? A : g_oh;

    // loader assignments: thread -> (tile row/col = tid/2, k-offset = (tid&1)*4)
    int lr = tid >> 1;
    int lk = (tid & 1) * 4;
    const float* arow = Ap + (size_t)(row0 + lr) * 256 + lk;
    int c = col0 + lr;
    const float* wrow;
    if (mode == 0) wrow = (c < 512) ? (W0 + (size_t)c * 256 + lk)
                                    : (W1 + (size_t)(c - 512) * 256 + lk);
    else           wrow = W0 + (size_t)c * 256 + lk;

    float acc[8][8];
    #pragma unroll
    for (int i = 0; i < 8; i++)
        #pragma unroll
        for (int j = 0; j < 8; j++) acc[i][j] = 0.f;

    for (int k0 = 0; k0 < 256; k0 += 8) {
        float4 av = *(const float4*)(arow + k0);
        float4 bv = *(const float4*)(wrow + k0);
        As[lk+0][lr] = av.x; As[lk+1][lr] = av.y; As[lk+2][lr] = av.z; As[lk+3][lr] = av.w;
        Bs[lk+0][lr] = bv.x; Bs[lk+1][lr] = bv.y; Bs[lk+2][lr] = bv.z; Bs[lk+3][lr] = bv.w;
        __syncthreads();
        #pragma unroll
        for (int kk = 0; kk < 8; kk++) {
            float4 a0 = *(const float4*)&As[kk][ty*4];
            float4 a1 = *(const float4*)&As[kk][64 + ty*4];
            float4 b0 = *(const float4*)&Bs[kk][tx*4];
            float4 b1 = *(const float4*)&Bs[kk][64 + tx*4];
            float a[8] = {a0.x,a0.y,a0.z,a0.w, a1.x,a1.y,a1.z,a1.w};
            float b[8] = {b0.x,b0.y,b0.z,b0.w, b1.x,b1.y,b1.z,b1.w};
            #pragma unroll
            for (int i = 0; i < 8; i++)
                #pragma unroll
                for (int j = 0; j < 8; j++)
                    acc[i][j] = fmaf(a[i], b[j], acc[i][j]);
        }
        __syncthreads();
    }

    #pragma unroll
    for (int i = 0; i < 8; i++) {
        int r = row0 + ((i < 4) ? (ty*4 + i) : (64 + ty*4 + i - 4));
        int bidx = r / Nn, n = r % Nn;
        #pragma unroll
        for (int j = 0; j < 8; j++) {
            int col = col0 + ((j < 4) ? (tx*4 + j) : (64 + tx*4 + j - 4));
            float val = acc[i][j];
            if (mode == 0) {
                int d = col & 31;
                if (col < 512) {
                    int h = (col >> 5) & 7;
                    float* dst = (col < 256) ? g_q : g_k;
                    dst[(((size_t)bidx*Hh + h)*Nn + n)*HD + d] = val;
                } else {
                    int h = (col - 512) >> 5;
                    g_v[(((size_t)bidx*Hh + h)*Nn + n)*HD + d] = val;
                }
            } else {
                out[(size_t)r * 256 + col] = val + bias[col];
            }
        }
    }
}

// =====================================================================
// Attention: one CTA per (b,h). K/V resident in smem (padded rows),
// 8 warps, each warp processes one query at a time.
// attn = (1-g)*softmax(QK^T/sqrt(hd)) + g*pos   (rows sum to exactly 1,
// so the reference's renormalization is a divide-by-1: skipped)
// =====================================================================
#define KPAD 36
#define SM_KS 0
#define SM_VS (Nn*KPAD)
#define SM_QS (2*Nn*KPAD)
#define SM_AT (2*Nn*KPAD + 8*HD)
#define SMEM_FLOATS (2*Nn*KPAD + 8*HD + 8*Nn)

__global__ __launch_bounds__(256)
void attn_kernel(const float* __restrict__ gating)
{
    extern __shared__ float sm[];
    float* ks = sm + SM_KS;
    float* vs = sm + SM_VS;
    float* qs = sm + SM_QS;
    float* at = sm + SM_AT;

    int bh = blockIdx.x;                 // b*8 + h
    int h  = bh & 7, bidx = bh >> 3;
    int tid = threadIdx.x, wid = tid >> 5, lane = tid & 31;

    const float* kg = g_k + (size_t)bh * Nn * HD;
    const float* vg = g_v + (size_t)bh * Nn * HD;
    const float* qg = g_q + (size_t)bh * Nn * HD;

    // stage K,V into padded smem (conflict-free per-row access later)
    for (int i = tid; i < Nn * HD / 4; i += 256) {
        int m = i >> 3, d = (i & 7) * 4;
        *(float4*)(ks + m*KPAD + d) = *(const float4*)(kg + m*HD + d);
        *(float4*)(vs + m*KPAD + d) = *(const float4*)(vg + m*HD + d);
    }
    __syncthreads();

    float g = 1.0f / (1.0f + __expf(-gating[h]));
    const float scale = 0.17677669529663687f;   // 1/sqrt(32)
    float* myq = qs + wid * HD;
    float* myat = at + wid * Nn;

    for (int n = wid; n < Nn; n += 8) {
        myq[lane] = qg[n*HD + lane];
        __syncwarp();
        float qr[HD];
        #pragma unroll
        for (int d = 0; d < HD; d++) qr[d] = myq[d];

        // scores for m = t*32 + lane
        float sreg[10], mx = -1e30f;
        #pragma unroll
        for (int t = 0; t < 10; t++) {
            int m = t*32 + lane;
            float s = -1e30f;
            if (m < Nn) {
                const float4* kr = (const float4*)(ks + m*KPAD);
                float acc = 0.f;
                #pragma unroll
                for (int dd = 0; dd < 8; dd++) {
                    float4 kv = kr[dd];
                    acc = fmaf(qr[4*dd+0], kv.x, acc);
                    acc = fmaf(qr[4*dd+1], kv.y, acc);
                    acc = fmaf(qr[4*dd+2], kv.z, acc);
                    acc = fmaf(qr[4*dd+3], kv.w, acc);
                }
                s = acc * scale;
            }
            sreg[t] = s; mx = fmaxf(mx, s);
        }
        #pragma unroll
        for (int o = 16; o; o >>= 1) mx = fmaxf(mx, __shfl_xor_sync(0xffffffffu, mx, o));
        float ereg[10], esum = 0.f;
        #pragma unroll
        for (int t = 0; t < 10; t++) { ereg[t] = __expf(sreg[t] - mx); esum += ereg[t]; }
        #pragma unroll
        for (int o = 16; o; o >>= 1) esum += __shfl_xor_sync(0xffffffffu, esum, o);
        float inv = (1.0f - g) / esum;

        const float* posrow = g_pos + ((size_t)h * Nn + n) * Nn;
        #pragma unroll
        for (int t = 0; t < 10; t++) {
            int m = t*32 + lane;
            if (m < Nn) myat[m] = fmaf(ereg[t], inv, g * posrow[m]);
        }
        __syncwarp();

        // O[n][lane] = sum_m attn[m] * V[m][lane]
        float acc = 0.f;
        #pragma unroll 4
        for (int m = 0; m < Nn; m += 4) {
            float4 a4 = *(const float4*)(myat + m);   // broadcast
            acc = fmaf(a4.x, vs[(m+0)*KPAD + lane], acc);
            acc = fmaf(a4.y, vs[(m+1)*KPAD + lane], acc);
            acc = fmaf(a4.z, vs[(m+2)*KPAD + lane], acc);
            acc = fmaf(a4.w, vs[(m+3)*KPAD + lane], acc);
        }
        g_oh[((size_t)bidx*Nn + n)*Cc + h*HD + lane] = acc;
        __syncwarp();
    }
}

// =====================================================================
extern "C" void kernel_launch(void* const* d_in, const int* in_sizes, int n_in,
                              void* d_out, int out_size)
{
    const float* x      = (const float*)d_in[0];
    const float* Wqk    = (const float*)d_in[1];
    const float* Wv     = (const float*)d_in[2];
    const float* Wpos   = (const float*)d_in[3];
    const float* bpos   = (const float*)d_in[4];
    const float* Wproj  = (const float*)d_in[5];
    const float* bproj  = (const float*)d_in[6];
    const float* gating = (const float*)d_in[7];
    float* out = (float*)d_out;

    size_t smem_bytes = SMEM_FLOATS * sizeof(float);   // ~97 KB
    cudaFuncSetAttribute(attn_kernel, cudaFuncAttributeMaxDynamicSharedMemorySize,
                         (int)smem_bytes);

    // 1) positional softmax (independent of x)
    pos_kernel<<<(Hh*Nn + 3) / 4, 128>>>(Wpos, bpos);

    // 2) QKV projection: [19200,256] @ [768,256]^T
    dim3 g1(6, ROWS / 128);
    gemm_kernel<<<g1, 256>>>(x, Wqk, Wv, nullptr, nullptr, 0);

    // 3) fused gated attention, one CTA per (b,h)
    attn_kernel<<<BH, 256, smem_bytes>>>(gating);

    // 4) output projection + bias
    dim3 g2(2, ROWS / 128);
    gemm_kernel<<<g2, 256>>>(nullptr, Wproj, nullptr, bproj, out, 1);
}

// round 2
// speedup vs baseline: 1.5556x; 1.5556x over previous
#include <cuda_runtime.h>
#include <math.h>

// ---------------- problem constants ----------------
#define Bb 64
#define Nn 300
#define Cc 256
#define Hh 8
#define HD 32
#define BH (Bb*Hh)          // 512
#define ROWS (Bb*Nn)        // 19200
#define QR 4                // queries per warp (register-blocked)
#define AW 16               // warps in attention CTA

// ---------------- scratch (device globals; no runtime alloc) ----------------
__device__ float g_q[BH * Nn * HD];     // [b,h,n,d]
__device__ float g_k[BH * Nn * HD];
__device__ float g_v[BH * Nn * HD];
__device__ float g_pos[Hh * Nn * Nn];   // softmaxed positional scores
__device__ float g_oh[ROWS * Cc];       // attention output, [b,n,h*32+d]

// =====================================================================
// positional score softmax. logit[h][n][m] = w0*d + w2*d^2 + b, d = m-n
// =====================================================================
__global__ void pos_kernel(const float* __restrict__ Wpos,
                           const float* __restrict__ bpos)
{
    int row  = blockIdx.x * 4 + (threadIdx.x >> 5);   // h*300 + n
    int lane = threadIdx.x & 31;
    if (row >= Hh * Nn) return;
    int h = row / Nn, n = row % Nn;
    float w0 = Wpos[h*3+0], w2 = Wpos[h*3+2], b = bpos[h];

    float s[10], mx = -1e30f;
    #pragma unroll
    for (int t = 0; t < 10; t++) {
        int m = t*32 + lane;
        float v = -1e30f;
        if (m < Nn) { float d = (float)(m - n); v = fmaf(w2*d, d, fmaf(w0, d, b)); }
        s[t] = v; mx = fmaxf(mx, v);
    }
    #pragma unroll
    for (int o = 16; o; o >>= 1) mx = fmaxf(mx, __shfl_xor_sync(0xffffffffu, mx, o));
    float e[10], esum = 0.f;
    #pragma unroll
    for (int t = 0; t < 10; t++) { e[t] = __expf(s[t] - mx); esum += e[t]; }
    #pragma unroll
    for (int o = 16; o; o >>= 1) esum += __shfl_xor_sync(0xffffffffu, esum, o);
    float inv = 1.0f / esum;
    float* dst = g_pos + row * Nn;
    #pragma unroll
    for (int t = 0; t < 10; t++) {
        int m = t*32 + lane;
        if (m < Nn) dst[m] = e[t] * inv;
    }
}

// =====================================================================
// GEMM: out[M,Ncols] = A[M,256] @ W[Ncols,256]^T
// 128x128 tile, KTILE=16, double-buffered smem, 8x8 per thread.
// mode 0: A=x, W=[Wqk;Wv], scatter into g_q/g_k/g_v
// mode 1: A=g_oh, W=Wproj, out = val + bias
// =====================================================================
#define KT 16
__global__ __launch_bounds__(256, 2)
void gemm_kernel(const float* __restrict__ A,
                 const float* __restrict__ W0,
                 const float* __restrict__ W1,
                 const float* __restrict__ bias,
                 float* __restrict__ out,
                 int mode)
{
    __shared__ float As[2][KT][132];
    __shared__ float Bs[2][KT][132];

    int tid  = threadIdx.x;
    int row0 = blockIdx.y * 128;
    int col0 = blockIdx.x * 128;
    int tx = tid & 15, ty = tid >> 4;

    const float* Ap = (mode == 0) ? A : g_oh;

    // loader: thread -> (tile row/col = tid/2, k-offset = (tid&1)*8)
    int lr = tid >> 1;
    int lk = (tid & 1) * 8;
    const float* arow = Ap + (size_t)(row0 + lr) * 256 + lk;
    int c = col0 + lr;
    const float* wrow;
    if (mode == 0) wrow = (c < 512) ? (W0 + (size_t)c * 256 + lk)
                                    : (W1 + (size_t)(c - 512) * 256 + lk);
    else           wrow = W0 + (size_t)c * 256 + lk;

    float acc[8][8];
    #pragma unroll
    for (int i = 0; i < 8; i++)
        #pragma unroll
        for (int j = 0; j < 8; j++) acc[i][j] = 0.f;

    float4 ra0, ra1, rb0, rb1;
    // prologue: tile 0
    ra0 = *(const float4*)(arow + 0);
    ra1 = *(const float4*)(arow + 4);
    rb0 = *(const float4*)(wrow + 0);
    rb1 = *(const float4*)(wrow + 4);
    int buf = 0;
    {
        As[0][lk+0][lr]=ra0.x; As[0][lk+1][lr]=ra0.y; As[0][lk+2][lr]=ra0.z; As[0][lk+3][lr]=ra0.w;
        As[0][lk+4][lr]=ra1.x; As[0][lk+5][lr]=ra1.y; As[0][lk+6][lr]=ra1.z; As[0][lk+7][lr]=ra1.w;
        Bs[0][lk+0][lr]=rb0.x; Bs[0][lk+1][lr]=rb0.y; Bs[0][lk+2][lr]=rb0.z; Bs[0][lk+3][lr]=rb0.w;
        Bs[0][lk+4][lr]=rb1.x; Bs[0][lk+5][lr]=rb1.y; Bs[0][lk+6][lr]=rb1.z; Bs[0][lk+7][lr]=rb1.w;
    }
    __syncthreads();

    for (int k0 = 0; k0 < 256; k0 += KT) {
        bool has_next = (k0 + KT) < 256;
        if (has_next) {
            ra0 = *(const float4*)(arow + k0 + KT + 0);
            ra1 = *(const float4*)(arow + k0 + KT + 4);
            rb0 = *(const float4*)(wrow + k0 + KT + 0);
            rb1 = *(const float4*)(wrow + k0 + KT + 4);
        }
        #pragma unroll
        for (int kk = 0; kk < KT; kk++) {
            float4 a0 = *(const float4*)&As[buf][kk][ty*4];
            float4 a1 = *(const float4*)&As[buf][kk][64 + ty*4];
            float4 b0 = *(const float4*)&Bs[buf][kk][tx*4];
            float4 b1 = *(const float4*)&Bs[buf][kk][64 + tx*4];
            float a[8] = {a0.x,a0.y,a0.z,a0.w, a1.x,a1.y,a1.z,a1.w};
            float b[8] = {b0.x,b0.y,b0.z,b0.w, b1.x,b1.y,b1.z,b1.w};
            #pragma unroll
            for (int i = 0; i < 8; i++)
                #pragma unroll
                for (int j = 0; j < 8; j++)
                    acc[i][j] = fmaf(a[i], b[j], acc[i][j]);
        }
        if (has_next) {
            int nb = buf ^ 1;
            As[nb][lk+0][lr]=ra0.x; As[nb][lk+1][lr]=ra0.y; As[nb][lk+2][lr]=ra0.z; As[nb][lk+3][lr]=ra0.w;
            As[nb][lk+4][lr]=ra1.x; As[nb][lk+5][lr]=ra1.y; As[nb][lk+6][lr]=ra1.z; As[nb][lk+7][lr]=ra1.w;
            Bs[nb][lk+0][lr]=rb0.x; Bs[nb][lk+1][lr]=rb0.y; Bs[nb][lk+2][lr]=rb0.z; Bs[nb][lk+3][lr]=rb0.w;
            Bs[nb][lk+4][lr]=rb1.x; Bs[nb][lk+5][lr]=rb1.y; Bs[nb][lk+6][lr]=rb1.z; Bs[nb][lk+7][lr]=rb1.w;
            __syncthreads();
            buf = nb;
        }
    }

    #pragma unroll
    for (int i = 0; i < 8; i++) {
        int r = row0 + ((i < 4) ? (ty*4 + i) : (64 + ty*4 + i - 4));
        int bidx = r / Nn, n = r % Nn;
        #pragma unroll
        for (int j = 0; j < 8; j++) {
            int col = col0 + ((j < 4) ? (tx*4 + j) : (64 + tx*4 + j - 4));
            float val = acc[i][j];
            if (mode == 0) {
                int d = col & 31;
                if (col < 512) {
                    int h = (col >> 5) & 7;
                    float* dst = (col < 256) ? g_q : g_k;
                    dst[(((size_t)bidx*Hh + h)*Nn + n)*HD + d] = val;
                } else {
                    int h = (col - 512) >> 5;
                    g_v[(((size_t)bidx*Hh + h)*Nn + n)*HD + d] = val;
                }
            } else {
                out[(size_t)r * 256 + col] = val + bias[col];
            }
        }
    }
}

// =====================================================================
// Attention: one CTA per (b,h). 16 warps, QR=4 queries per warp
// (register-blocked so each K/V smem load amortizes over 4 queries).
// attn = (1-g)*softmax(QK^T/sqrt(hd)) + g*pos  (rows sum to 1 -> no renorm)
// =====================================================================
#define KPAD 36
#define SM_VS (Nn*KPAD)
#define SM_QS (2*Nn*KPAD)
#define SM_AT (2*Nn*KPAD + AW*QR*HD)
#define SMEM_FLOATS (2*Nn*KPAD + AW*QR*HD + AW*QR*Nn)

__global__ __launch_bounds__(AW*32)
void attn_kernel(const float* __restrict__ gating)
{
    extern __shared__ float sm[];
    float* ks = sm;
    float* vs = sm + SM_VS;
    float* qs = sm + SM_QS;                   // [wid][qq][32]
    float* at = sm + SM_AT;                   // [wid][qq][300]

    int bh = blockIdx.x;                 // b*8 + h
    int h  = bh & 7, bidx = bh >> 3;
    int tid = threadIdx.x, wid = tid >> 5, lane = tid & 31;

    const float* kg = g_k + (size_t)bh * Nn * HD;
    const float* vg = g_v + (size_t)bh * Nn * HD;
    const float* qg = g_q + (size_t)bh * Nn * HD;

    // stage K,V into padded smem
    for (int i = tid; i < Nn * HD / 4; i += AW*32) {
        int m = i >> 3, d = (i & 7) * 4;
        *(float4*)(ks + m*KPAD + d) = *(const float4*)(kg + m*HD + d);
        *(float4*)(vs + m*KPAD + d) = *(const float4*)(vg + m*HD + d);
    }
    __syncthreads();

    float g = 1.0f / (1.0f + __expf(-gating[h]));
    const float scale = 0.17677669529663687f;   // 1/sqrt(32)
    float* myq  = qs + wid * (QR*HD);
    float* myat = at + wid * (QR*Nn);

    // n0 takes values wid*4 + 64k < 300 -> all 4 queries always valid
    for (int n0 = wid*QR; n0 < Nn; n0 += AW*QR) {
        #pragma unroll
        for (int qq = 0; qq < QR; qq++)
            myq[qq*HD + lane] = qg[(n0+qq)*HD + lane];
        __syncwarp();

        // ---- scores: acc[qq][t], m = t*32+lane ----
        float acc[QR][10];
        #pragma unroll
        for (int qq = 0; qq < QR; qq++)
            #pragma unroll
            for (int t = 0; t < 10; t++) acc[qq][t] = 0.f;

        #pragma unroll
        for (int dd = 0; dd < 8; dd++) {
            float4 qv[QR];
            #pragma unroll
            for (int qq = 0; qq < QR; qq++)
                qv[qq] = *(const float4*)&myq[qq*HD + dd*4];
            #pragma unroll
            for (int t = 0; t < 10; t++) {
                int m = t*32 + lane;
                float4 kv = *(const float4*)&ks[m*KPAD + dd*4];  // m<320 stays in smem
                #pragma unroll
                for (int qq = 0; qq < QR; qq++) {
                    acc[qq][t] = fmaf(qv[qq].x, kv.x, acc[qq][t]);
                    acc[qq][t] = fmaf(qv[qq].y, kv.y, acc[qq][t]);
                    acc[qq][t] = fmaf(qv[qq].z, kv.z, acc[qq][t]);
                    acc[qq][t] = fmaf(qv[qq].w, kv.w, acc[qq][t]);
                }
            }
        }

        // ---- softmax + gate-mix per query ----
        #pragma unroll
        for (int qq = 0; qq < QR; qq++) {
            int n = n0 + qq;
            float mx = -1e30f;
            #pragma unroll
            for (int t = 0; t < 10; t++) {
                int m = t*32 + lane;
                float s = (m < Nn) ? acc[qq][t] * scale : -1e30f;
                acc[qq][t] = s;
                mx = fmaxf(mx, s);
            }
            #pragma unroll
            for (int o = 16; o; o >>= 1) mx = fmaxf(mx, __shfl_xor_sync(0xffffffffu, mx, o));
            float esum = 0.f;
            #pragma unroll
            for (int t = 0; t < 10; t++) {
                float e = __expf(acc[qq][t] - mx);
                acc[qq][t] = e; esum += e;
            }
            #pragma unroll
            for (int o = 16; o; o >>= 1) esum += __shfl_xor_sync(0xffffffffu, esum, o);
            float inv = (1.0f - g) / esum;

            const float* posrow = g_pos + ((size_t)h * Nn + n) * Nn;
            #pragma unroll
            for (int t = 0; t < 10; t++) {
                int m = t*32 + lane;
                if (m < Nn) myat[qq*Nn + m] = fmaf(acc[qq][t], inv, g * posrow[m]);
            }
        }
        __syncwarp();

        // ---- O[n][lane] = sum_m attn[n][m] * V[m][lane] ----
        float o[QR] = {0.f, 0.f, 0.f, 0.f};
        #pragma unroll 3
        for (int m0 = 0; m0 < Nn; m0 += 4) {
            float4 a[QR];
            #pragma unroll
            for (int qq = 0; qq < QR; qq++)
                a[qq] = *(const float4*)&myat[qq*Nn + m0];       // broadcast
            float v0 = vs[(m0+0)*KPAD + lane];
            float v1 = vs[(m0+1)*KPAD + lane];
            float v2 = vs[(m0+2)*KPAD + lane];
            float v3 = vs[(m0+3)*KPAD + lane];
            #pragma unroll
            for (int qq = 0; qq < QR; qq++) {
                o[qq] = fmaf(a[qq].x, v0, o[qq]);
                o[qq] = fmaf(a[qq].y, v1, o[qq]);
                o[qq] = fmaf(a[qq].z, v2, o[qq]);
                o[qq] = fmaf(a[qq].w, v3, o[qq]);
            }
        }
        #pragma unroll
        for (int qq = 0; qq < QR; qq++)
            g_oh[((size_t)bidx*Nn + (n0+qq))*Cc + h*HD + lane] = o[qq];
        __syncwarp();
    }
}

// =====================================================================
extern "C" void kernel_launch(void* const* d_in, const int* in_sizes, int n_in,
                              void* d_out, int out_size)
{
    const float* x      = (const float*)d_in[0];
    const float* Wqk    = (const float*)d_in[1];
    const float* Wv     = (const float*)d_in[2];
    const float* Wpos   = (const float*)d_in[3];
    const float* bpos   = (const float*)d_in[4];
    const float* Wproj  = (const float*)d_in[5];
    const float* bproj  = (const float*)d_in[6];
    const float* gating = (const float*)d_in[7];
    float* out = (float*)d_out;

    size_t smem_bytes = SMEM_FLOATS * sizeof(float);   // ~171 KB
    cudaFuncSetAttribute(attn_kernel, cudaFuncAttributeMaxDynamicSharedMemorySize,
                         (int)smem_bytes);

    // 1) positional softmax (independent of x)
    pos_kernel<<<(Hh*Nn + 3) / 4, 128>>>(Wpos, bpos);

    // 2) QKV projection: [19200,256] @ [768,256]^T
    dim3 g1(6, ROWS / 128);
    gemm_kernel<<<g1, 256>>>(x, Wqk, Wv, nullptr, nullptr, 0);

    // 3) fused gated attention, one CTA per (b,h)
    attn_kernel<<<BH, AW*32, smem_bytes>>>(gating);

    // 4) output projection + bias
    dim3 g2(2, ROWS / 128);
    gemm_kernel<<<g2, 256>>>(nullptr, Wproj, nullptr, bproj, out, 1);
}

// round 6
// speedup vs baseline: 1.5693x; 1.0088x over previous
#include <cuda_runtime.h>
#include <math.h>
#include <stdint.h>

// ---------------- problem constants ----------------
#define Bb 64
#define Nn 300
#define Cc 256
#define Hh 8
#define HD 32
#define BH (Bb*Hh)          // 512
#define ROWS (Bb*Nn)        // 19200
#define QR 8                // queries per warp (register-blocked)
#define AW 12               // warps in attention CTA

// ---------------- scratch (device globals; no runtime alloc) ----------------
__device__ float g_q[BH * Nn * HD];     // [b,h,n,d]
__device__ float g_k[BH * Nn * HD];
__device__ float g_v[BH * Nn * HD];
__device__ float g_posmx[Hh * Nn];      // per-(h,n) positional logit max
__device__ float g_posinv[Hh * Nn];     // g(h) / sum(exp(logit - max))
__device__ float g_oh[ROWS * Cc];       // attention output, [b,n,h*32+d]

// ---------------- packed f32x2 helpers ----------------
__device__ __forceinline__ unsigned long long pk2(float x, float y) {
    unsigned long long r;
    asm("mov.b64 %0, {%1,%2};" : "=l"(r)
        : "r"(__float_as_uint(x)), "r"(__float_as_uint(y)));
    return r;
}
__device__ __forceinline__ void fma2(unsigned long long& d,
                                     unsigned long long a, unsigned long long b) {
    asm("fma.rn.f32x2 %0, %1, %2, %0;" : "+l"(d) : "l"(a), "l"(b));
}
__device__ __forceinline__ void upk2(float& lo, float& hi, unsigned long long v) {
    uint32_t l, h;
    asm("mov.b64 {%0,%1}, %2;" : "=r"(l), "=r"(h) : "l"(v));
    lo = __uint_as_float(l); hi = __uint_as_float(h);
}

// =====================================================================
// positional softmax stats: logit[h][n][m] = w0*d + w2*d^2 + b, d = m-n.
// Emits only max and g/sum per (h,n); weights reconstructed in attention.
// =====================================================================
__global__ void pos_kernel(const float* __restrict__ Wpos,
                           const float* __restrict__ bpos,
                           const float* __restrict__ gating)
{
    int row  = blockIdx.x * 4 + (threadIdx.x >> 5);   // h*300 + n
    int lane = threadIdx.x & 31;
    if (row >= Hh * Nn) return;
    int h = row / Nn, n = row % Nn;
    float w0 = Wpos[h*3+0], w2 = Wpos[h*3+2], b = bpos[h];

    float s[10], mx = -1e30f;
    #pragma unroll
    for (int t = 0; t < 10; t++) {
        int m = t*32 + lane;
        float v = -1e30f;
        if (m < Nn) { float d = (float)(m - n); v = fmaf(w2*d, d, fmaf(w0, d, b)); }
        s[t] = v; mx = fmaxf(mx, v);
    }
    #pragma unroll
    for (int o = 16; o; o >>= 1) mx = fmaxf(mx, __shfl_xor_sync(0xffffffffu, mx, o));
    float esum = 0.f;
    #pragma unroll
    for (int t = 0; t < 10; t++) esum += __expf(s[t] - mx);
    #pragma unroll
    for (int o = 16; o; o >>= 1) esum += __shfl_xor_sync(0xffffffffu, esum, o);
    if (lane == 0) {
        float g = 1.0f / (1.0f + __expf(-gating[h]));
        g_posmx[row]  = mx;
        g_posinv[row] = g / esum;
    }
}

// =====================================================================
// GEMM: out[M,Ncols] = A[M,256] @ W[Ncols,256]^T
// 128x128 tile, KT=16 double-buffered smem, 8x8/thr, FFMA2 over col-pairs.
// mode 0: A=x, W=[Wqk;Wv], scatter into g_q/g_k/g_v
// mode 1: A=g_oh, W=Wproj, out = val + bias
// =====================================================================
#define KT 16
__global__ __launch_bounds__(256, 2)
void gemm_kernel(const float* __restrict__ A,
                 const float* __restrict__ W0,
                 const float* __restrict__ W1,
                 const float* __restrict__ bias,
                 float* __restrict__ out,
                 int mode)
{
    __shared__ __align__(16) float As[2][KT][132];
    __shared__ __align__(16) float Bs[2][KT][132];

    int tid  = threadIdx.x;
    int row0 = blockIdx.y * 128;
    int col0 = blockIdx.x * 128;
    int tx = tid & 15, ty = tid >> 4;

    const float* Ap = (mode == 0) ? A : g_oh;

    int lr = tid >> 1;
    int lk = (tid & 1) * 8;
    const float* arow = Ap + (size_t)(row0 + lr) * 256 + lk;
    int c = col0 + lr;
    const float* wrow;
    if (mode == 0) wrow = (c < 512) ? (W0 + (size_t)c * 256 + lk)
                                    : (W1 + (size_t)(c - 512) * 256 + lk);
    else           wrow = W0 + (size_t)c * 256 + lk;

    unsigned long long acc2[8][4];     // [row i][col-pair jp]
    #pragma unroll
    for (int i = 0; i < 8; i++)
        #pragma unroll
        for (int jp = 0; jp < 4; jp++) acc2[i][jp] = 0ULL;

    float4 ra0, ra1, rb0, rb1;
    ra0 = *(const float4*)(arow + 0);
    ra1 = *(const float4*)(arow + 4);
    rb0 = *(const float4*)(wrow + 0);
    rb1 = *(const float4*)(wrow + 4);
    int buf = 0;
    {
        As[0][lk+0][lr]=ra0.x; As[0][lk+1][lr]=ra0.y; As[0][lk+2][lr]=ra0.z; As[0][lk+3][lr]=ra0.w;
        As[0][lk+4][lr]=ra1.x; As[0][lk+5][lr]=ra1.y; As[0][lk+6][lr]=ra1.z; As[0][lk+7][lr]=ra1.w;
        Bs[0][lk+0][lr]=rb0.x; Bs[0][lk+1][lr]=rb0.y; Bs[0][lk+2][lr]=rb0.z; Bs[0][lk+3][lr]=rb0.w;
        Bs[0][lk+4][lr]=rb1.x; Bs[0][lk+5][lr]=rb1.y; Bs[0][lk+6][lr]=rb1.z; Bs[0][lk+7][lr]=rb1.w;
    }
    __syncthreads();

    for (int k0 = 0; k0 < 256; k0 += KT) {
        bool has_next = (k0 + KT) < 256;
        if (has_next) {
            ra0 = *(const float4*)(arow + k0 + KT + 0);
            ra1 = *(const float4*)(arow + k0 + KT + 4);
            rb0 = *(const float4*)(wrow + k0 + KT + 0);
            rb1 = *(const float4*)(wrow + k0 + KT + 4);
        }
        #pragma unroll
        for (int kk = 0; kk < KT; kk++) {
            float4 a0 = *(const float4*)&As[buf][kk][ty*4];
            float4 a1 = *(const float4*)&As[buf][kk][64 + ty*4];
            ulonglong2 bb0 = *(const ulonglong2*)&Bs[buf][kk][tx*4];
            ulonglong2 bb1 = *(const ulonglong2*)&Bs[buf][kk][64 + tx*4];
            unsigned long long bp[4] = {bb0.x, bb0.y, bb1.x, bb1.y};
            float a[8] = {a0.x,a0.y,a0.z,a0.w, a1.x,a1.y,a1.z,a1.w};
            #pragma unroll
            for (int i = 0; i < 8; i++) {
                unsigned long long ap = pk2(a[i], a[i]);
                #pragma unroll
                for (int jp = 0; jp < 4; jp++)
                    fma2(acc2[i][jp], ap, bp[jp]);
            }
        }
        if (has_next) {
            int nb = buf ^ 1;
            As[nb][lk+0][lr]=ra0.x; As[nb][lk+1][lr]=ra0.y; As[nb][lk+2][lr]=ra0.z; As[nb][lk+3][lr]=ra0.w;
            As[nb][lk+4][lr]=ra1.x; As[nb][lk+5][lr]=ra1.y; As[nb][lk+6][lr]=ra1.z; As[nb][lk+7][lr]=ra1.w;
            Bs[nb][lk+0][lr]=rb0.x; Bs[nb][lk+1][lr]=rb0.y; Bs[nb][lk+2][lr]=rb0.z; Bs[nb][lk+3][lr]=rb0.w;
            Bs[nb][lk+4][lr]=rb1.x; Bs[nb][lk+5][lr]=rb1.y; Bs[nb][lk+6][lr]=rb1.z; Bs[nb][lk+7][lr]=rb1.w;
            __syncthreads();
            buf = nb;
        }
    }

    #pragma unroll
    for (int i = 0; i < 8; i++) {
        int r = row0 + ((i < 4) ? (ty*4 + i) : (64 + ty*4 + i - 4));
        int bidx = r / Nn, n = r % Nn;
        #pragma unroll
        for (int jp = 0; jp < 4; jp++) {
            int col = col0 + ((jp < 2) ? (tx*4 + jp*2) : (64 + tx*4 + (jp-2)*2));
            float d0, d1; upk2(d0, d1, acc2[i][jp]);
            if (mode == 0) {
                int d = col & 31;
                if (col < 512) {
                    int h = (col >> 5) & 7;
                    float* dst = (col < 256) ? g_q : g_k;
                    *(float2*)(dst + (((size_t)bidx*Hh + h)*Nn + n)*HD + d) = make_float2(d0, d1);
                } else {
                    int h = (col - 512) >> 5;
                    *(float2*)(g_v + (((size_t)bidx*Hh + h)*Nn + n)*HD + d) = make_float2(d0, d1);
                }
            } else {
                *(float2*)(out + (size_t)r * 256 + col) =
                    make_float2(d0 + bias[col], d1 + bias[col + 1]);
            }
        }
    }
}

// =====================================================================
// Attention: one CTA per (b,h). 12 warps, QR=8 queries per warp.
// QK paired over query-pairs (FFMA2); AV paired over m; pos weights
// reconstructed inline from (max, g/sum) stats.
// attn = (1-g)*softmax(QK^T*scale) + g*pos  (rows sum to 1 -> no renorm)
// =====================================================================
#define KPAD 33
#define SM_VS (Nn*KPAD)                  // 9900
#define SM_QS (2*Nn*KPAD)                // 19800
#define SM_AT (SM_QS + AW*QR*HD)         // 22872
#define SMEM_FLOATS (SM_AT + AW*QR*Nn)   // 51672 (~207 KB)

__global__ __launch_bounds__(AW*32)
void attn_kernel(const float* __restrict__ Wpos,
                 const float* __restrict__ bpos,
                 const float* __restrict__ gating)
{
    extern __shared__ float sm[];
    float* ks = sm;
    float* vs = sm + SM_VS;
    float* qs = sm + SM_QS;            // [wid][d][qq] interleaved
    float* at = sm + SM_AT;            // [wid][qq][300]

    int bh = blockIdx.x;               // b*8 + h
    int h  = bh & 7, bidx = bh >> 3;
    int tid = threadIdx.x, wid = tid >> 5, lane = tid & 31;

    const float* kg = g_k + (size_t)bh * Nn * HD;
    const float* vg = g_v + (size_t)bh * Nn * HD;
    const float* qg = g_q + (size_t)bh * Nn * HD;

    // stage K,V (scalar stores; KPAD=33 -> conflict-free scalar access)
    for (int i = tid; i < Nn * HD / 4; i += AW*32) {
        int m = i >> 3, d = (i & 7) * 4;
        float4 kv4 = *(const float4*)(kg + m*HD + d);
        float4 vv4 = *(const float4*)(vg + m*HD + d);
        ks[m*KPAD + d + 0] = kv4.x; ks[m*KPAD + d + 1] = kv4.y;
        ks[m*KPAD + d + 2] = kv4.z; ks[m*KPAD + d + 3] = kv4.w;
        vs[m*KPAD + d + 0] = vv4.x; vs[m*KPAD + d + 1] = vv4.y;
        vs[m*KPAD + d + 2] = vv4.z; vs[m*KPAD + d + 3] = vv4.w;
    }
    __syncthreads();

    float g  = 1.0f / (1.0f + __expf(-gating[h]));
    float w0 = Wpos[h*3+0], w2 = Wpos[h*3+2], bps = bpos[h];
    const float scale = 0.17677669529663687f;   // 1/sqrt(32)
    float* myq  = qs + wid * (QR*HD);
    float* myat = at + wid * (QR*Nn);

    for (int n0 = wid*QR; n0 < Nn; n0 += AW*QR) {
        // stage q interleaved: myq[d*QR + qq]
        #pragma unroll
        for (int qq = 0; qq < QR; qq++) {
            int n = n0 + qq; int nc = (n < Nn) ? n : (Nn-1);
            myq[lane*QR + qq] = qg[nc*HD + lane];
        }
        __syncwarp();

        // ---- QK: acc2[p][t] = {score(2p), score(2p+1)} at m=t*32+lane ----
        unsigned long long acc2[4][10];
        #pragma unroll
        for (int p = 0; p < 4; p++)
            #pragma unroll
            for (int t = 0; t < 10; t++) acc2[p][t] = 0ULL;

        #pragma unroll
        for (int d = 0; d < HD; d++) {
            ulonglong2 qa = *(const ulonglong2*)&myq[d*QR];      // pairs (0,1),(2,3)
            ulonglong2 qb = *(const ulonglong2*)&myq[d*QR + 4];  // pairs (4,5),(6,7)
            #pragma unroll
            for (int t = 0; t < 10; t++) {
                float kv = ks[(t*32 + lane)*KPAD + d];
                unsigned long long kp = pk2(kv, kv);
                fma2(acc2[0][t], qa.x, kp);
                fma2(acc2[1][t], qa.y, kp);
                fma2(acc2[2][t], qb.x, kp);
                fma2(acc2[3][t], qb.y, kp);
            }
        }

        // ---- softmax + gated mix per query ----
        #pragma unroll
        for (int p = 0; p < 4; p++) {
            #pragma unroll
            for (int half = 0; half < 2; half++) {
                int qq = p*2 + half;
                int n = n0 + qq; int nc = (n < Nn) ? n : (Nn-1);
                float s[10], mx = -1e30f;
                #pragma unroll
                for (int t = 0; t < 10; t++) {
                    float lo, hi; upk2(lo, hi, acc2[p][t]);
                    float v = half ? hi : lo;
                    int m = t*32 + lane;
                    v = (m < Nn) ? v * scale : -1e30f;
                    s[t] = v; mx = fmaxf(mx, v);
                }
                #pragma unroll
                for (int o = 16; o; o >>= 1) mx = fmaxf(mx, __shfl_xor_sync(0xffffffffu, mx, o));
                float esum = 0.f;
                #pragma unroll
                for (int t = 0; t < 10; t++) { s[t] = __expf(s[t] - mx); esum += s[t]; }
                #pragma unroll
                for (int o = 16; o; o >>= 1) esum += __shfl_xor_sync(0xffffffffu, esum, o);
                float inv  = (1.0f - g) / esum;
                float pmx  = g_posmx[h*Nn + nc];
                float pinv = g_posinv[h*Nn + nc];
                if (n < Nn) {
                    #pragma unroll
                    for (int t = 0; t < 10; t++) {
                        int m = t*32 + lane;
                        if (m < Nn) {
                            float dd = (float)(m - nc);
                            float pe = __expf(fmaf(w2*dd, dd, fmaf(w0, dd, bps)) - pmx) * pinv;
                            myat[qq*Nn + m] = fmaf(s[t], inv, pe);
                        }
                    }
                }
            }
        }
        __syncwarp();

        // ---- AV: o2[qq] = {sum even m, sum odd m} of attn*V[.,lane] ----
        unsigned long long o2[QR];
        #pragma unroll
        for (int qq = 0; qq < QR; qq++) o2[qq] = 0ULL;

        #pragma unroll 2
        for (int m0 = 0; m0 < Nn; m0 += 4) {
            float v0 = vs[(m0+0)*KPAD + lane];
            float v1 = vs[(m0+1)*KPAD + lane];
            float v2 = vs[(m0+2)*KPAD + lane];
            float v3 = vs[(m0+3)*KPAD + lane];
            unsigned long long vp01 = pk2(v0, v1);
            unsigned long long vp23 = pk2(v2, v3);
            #pragma unroll
            for (int qq = 0; qq < QR; qq++) {
                ulonglong2 a2 = *(const ulonglong2*)&myat[qq*Nn + m0];
                fma2(o2[qq], a2.x, vp01);
                fma2(o2[qq], a2.y, vp23);
            }
        }
        #pragma unroll
        for (int qq = 0; qq < QR; qq++) {
            int n = n0 + qq;
            if (n < Nn) {
                float lo, hi; upk2(lo, hi, o2[qq]);
                g_oh[((size_t)bidx*Nn + n)*Cc + h*HD + lane] = lo + hi;
            }
        }
        __syncwarp();
    }
}

// =====================================================================
extern "C" void kernel_launch(void* const* d_in, const int* in_sizes, int n_in,
                              void* d_out, int out_size)
{
    const float* x      = (const float*)d_in[0];
    const float* Wqk    = (const float*)d_in[1];
    const float* Wv     = (const float*)d_in[2];
    const float* Wpos   = (const float*)d_in[3];
    const float* bpos   = (const float*)d_in[4];
    const float* Wproj  = (const float*)d_in[5];
    const float* bproj  = (const float*)d_in[6];
    const float* gating = (const float*)d_in[7];
    float* out = (float*)d_out;

    size_t attn_smem = SMEM_FLOATS * sizeof(float);   // ~207 KB
    cudaFuncSetAttribute(attn_kernel, cudaFuncAttributeMaxDynamicSharedMemorySize,
                         (int)attn_smem);

    // 1) positional softmax stats (independent of x)
    pos_kernel<<<(Hh*Nn + 3) / 4, 128>>>(Wpos, bpos, gating);

    // 2) QKV projection: [19200,256] @ [768,256]^T
    dim3 g1(6, ROWS / 128);
    gemm_kernel<<<g1, 256>>>(x, Wqk, Wv, nullptr, nullptr, 0);

    // 3) fused gated attention, one CTA per (b,h)
    attn_kernel<<<BH, AW*32, attn_smem>>>(Wpos, bpos, gating);

    // 4) output projection + bias
    dim3 g2(2, ROWS / 128);
    gemm_kernel<<<g2, 256>>>(nullptr, Wproj, nullptr, bproj, out, 1);
}